// round 13
// baseline (speedup 1.0000x reference)
#include <cuda_runtime.h>
#include <cuda_fp16.h>
#include <stdint.h>

#define L   128
#define BZ  32
#define TT  512
#define DD  4096
#define MT  (TT*BZ)   // 16384 decoder rows

// ---------------- scratch (device globals; no allocation) ----------------
__device__ float g_h1p[8 * BZ * L];          // enc0 split-K partials
__device__ float g_z0[BZ * L];
__device__ float g_Kpow[9 * L * L];          // K^2 .. K^512
__device__ float g_Klo[16 * L * L];          // K^lo
__device__ float g_Phi[64 * L * BZ];         // (K^16)^hi @ z0^T, [hi][l][b]
__device__ __half g_Ah[MT * L];              // last hidden activations, fp16
__device__ __half g_Wh[DD * L];              // Wd3 transposed [n][k], fp16
__device__ __half g_Whid[3 * L * L];         // Wd0..2 transposed [n][k], fp16
__device__ int g_bar[16];                    // monotonic ticket barriers (never reset)

// ticket grid barrier: monotonic counter, safe across graph replays
__device__ __forceinline__ void gridbar(int* ctr, int n) {
    __threadfence();
    __syncthreads();
    if (threadIdx.x == 0) {
        int t = atomicAdd(ctr, 1);
        int target = (t / n + 1) * n;
        while (*(volatile int*)ctr < target) {}
        __threadfence();
    }
    __syncthreads();
}

// ================= launch 1: kpow(0..63) || encoder(64..191) || weight cvt(192..331) =================
// 256 threads, 64 KB dynamic smem -> 3 CTAs/SM -> 332 CTAs single wave.
__global__ __launch_bounds__(256)
void encKpow_kernel(const float* __restrict__ x0, const float* __restrict__ K1,
                    const float* __restrict__ W0, const float* __restrict__ b0,
                    const float* __restrict__ W1, const float* __restrict__ b1,
                    const float* __restrict__ W2, const float* __restrict__ b2,
                    const float* __restrict__ W3, const float* __restrict__ b3,
                    const float* __restrict__ Wd0, const float* __restrict__ Wd1,
                    const float* __restrict__ Wd2, const float* __restrict__ Wd3) {
    extern __shared__ float sm1[];
    int tid = threadIdx.x;     // 0..255
    int n   = tid & 127;
    int grp = tid >> 7;        // 0/1

    if (blockIdx.x < 64) {
        // ---- kpow chain: 2 rows per CTA, A smem-resident ----
        float* As = sm1;       // 64 KB
        float4* As4 = (float4*)As;
        int row = blockIdx.x * 2 + grp;
        const float* A = K1;
        for (int p = 0; p < 9; p++) {
            float* C = g_Kpow + (size_t)p * L * L;
            const float4* A4 = (const float4*)A;
#pragma unroll
            for (int q = tid; q < 4096; q += 256) As4[q] = A4[q];
            __syncthreads();
            const float* rowA = As + row * L;
            float a0 = 0.f, a1 = 0.f, a2 = 0.f, a3 = 0.f;
#pragma unroll 8
            for (int k = 0; k < L; k += 4) {
                a0 += rowA[k + 0] * As[(k + 0) * L + n];
                a1 += rowA[k + 1] * As[(k + 1) * L + n];
                a2 += rowA[k + 2] * As[(k + 2) * L + n];
                a3 += rowA[k + 3] * As[(k + 3) * L + n];
            }
            C[row * L + n] = (a0 + a1) + (a2 + a3);
            __syncthreads();
            gridbar(&g_bar[1 + p], 64);
            A = C;
        }
    } else if (blockIdx.x < 192) {
        // ---- encoder split-K: 2 jobs per CTA ----
        float* xs = sm1 + grp * 512;
        int job = (blockIdx.x - 64) * 2 + grp;
        int row = job >> 3, c = job & 7;

        {
            const float4* src = (const float4*)(x0 + (size_t)row * DD + c * 512);
            ((float4*)xs)[n] = src[n];
        }
        __syncthreads();
        float a0 = 0.f, a1 = 0.f, a2 = 0.f, a3 = 0.f;
        const float* Wc = W0 + (size_t)(c * 512) * L;
#pragma unroll 8
        for (int k = 0; k < 512; k += 4) {
            a0 += xs[k + 0] * Wc[(size_t)(k + 0) * L + n];
            a1 += xs[k + 1] * Wc[(size_t)(k + 1) * L + n];
            a2 += xs[k + 2] * Wc[(size_t)(k + 2) * L + n];
            a3 += xs[k + 3] * Wc[(size_t)(k + 3) * L + n];
        }
        g_h1p[(c * BZ + row) * L + n] = (a0 + a1) + (a2 + a3);

        gridbar(&g_bar[0], 128);
        if (blockIdx.x != 64) return;

        // ---- tail on one CTA ----
        float* Ws = sm1;                 // 32 KB half of W
        float* Xa = sm1 + 8192;
        float* Xb = sm1 + 12288;
        float4* Ws4 = (float4*)Ws;
        int r0 = grp * 16;

#pragma unroll
        for (int r = 0; r < 16; r++) {
            float s = 0.f;
#pragma unroll
            for (int c2 = 0; c2 < 8; c2++) s += g_h1p[(c2 * BZ + r0 + r) * L + n];
            Xa[(r0 + r) * L + n] = fmaxf(s + b0[n], 0.f);
        }
        __syncthreads();

        const float* Wl[3] = {W1, W2, W3};
        const float* bl[3] = {b1, b2, b3};
        float* Xi = Xa; float* Xo = Xb;
#pragma unroll
        for (int layer = 0; layer < 3; layer++) {
            float acc[16];
#pragma unroll
            for (int r = 0; r < 16; r++) acc[r] = 0.f;
#pragma unroll
            for (int half = 0; half < 2; half++) {
                const float4* W4 = (const float4*)(Wl[layer] + half * 64 * L);
#pragma unroll
                for (int q = tid; q < 2048; q += 256) Ws4[q] = W4[q];
                __syncthreads();
#pragma unroll 4
                for (int k = 0; k < 64; k++) {
                    float w = Ws[k * L + n];
#pragma unroll
                    for (int r = 0; r < 16; r++) acc[r] += Xi[(r0 + r) * L + half * 64 + k] * w;
                }
                __syncthreads();
            }
            float bn = bl[layer][n];
            if (layer < 2) {
#pragma unroll
                for (int r = 0; r < 16; r++) Xo[(r0 + r) * L + n] = fmaxf(acc[r] + bn, 0.f);
                __syncthreads();
                float* tp = Xi; Xi = Xo; Xo = tp;
            } else {
#pragma unroll
                for (int r = 0; r < 16; r++) g_z0[(r0 + r) * L + n] = acc[r] + bn;
            }
        }
        __threadfence();
    } else {
        // ---- weight transpose + fp16 convert ----
        float (*tile)[33] = (float(*)[33])sm1;
        const float* src;
        __half* dstg;
        int n0, stride;
        int u2 = blockIdx.x - 192;
        if (u2 < 128) {
            n0 = u2 * 32; src = Wd3; stride = DD; dstg = g_Wh;
        } else {
            int u3 = u2 - 128;
            int layer = u3 >> 2;
            n0 = (u3 & 3) * 32;
            src = (layer == 0) ? Wd0 : (layer == 1) ? Wd1 : Wd2;
            stride = L;
            dstg = g_Whid + (size_t)layer * L * L;
        }
        int tx = tid & 31, ty = tid >> 5;
        for (int k = ty; k < 128; k += 8)
            tile[k][tx] = src[(size_t)k * stride + n0 + tx];
        __syncthreads();
        int nn = n0 + (tid >> 3);
        int k0 = (tid & 7) * 16;
        int c  = nn - n0;
        __half2 h[8];
#pragma unroll
        for (int j = 0; j < 8; j++)
            h[j] = __floats2half2_rn(tile[k0 + 2 * j][c], tile[k0 + 2 * j + 1][c]);
        uint4* dh = (uint4*)(dstg + (size_t)nn * L + k0);
        dh[0] = ((uint4*)h)[0];
        dh[1] = ((uint4*)h)[1];
    }
}

// ================= launch 2: klo/phi (A0) + apply (A1) + fp16 hiddens (A2) + final GEMM (B) =================
#define SPE 136
#define TILE_BYTES (128 * SPE * 2)      // 34816
#define OFF_B   0
#define OFF_A0  TILE_BYTES
#define OFF_A1  (2 * TILE_BYTES)
#define FSM_BYTES (3 * TILE_BYTES)      // 104448

// phase-A scratch lives strictly ABOVE the B-weight tile [0, 34816) so the
// B cp.async issued at kernel entry streams in untouched.
#define AK_OFF    34816                  // 32 KB staging (K^lo / K halves / klo factor)
#define APHI_OFF  67584                  // 16 KB (sPhi) / 8KB+8KB (phi Z0/Z1, klo S/T)
#define XA2_OFF   87040                  // 64x136 fp16 act tile (17408 B) -> ends 104448
#define WH2_OFF   34816                  // A2 weight tile (34816 B) -> ends 69632
#define XB2_OFF   69632                  // A2 ping buffer (17408 B) -> ends 87040

__device__ __forceinline__ uint32_t smem_u32(const void* p) {
    uint32_t a;
    asm("{ .reg .u64 t; cvta.to.shared.u64 t, %1; cvt.u32.u64 %0, t; }" : "=r"(a) : "l"(p));
    return a;
}
__device__ __forceinline__ void cpasync16(uint32_t dst, const void* src) {
    asm volatile("cp.async.cg.shared.global [%0], [%1], 16;" :: "r"(dst), "l"(src));
}
__device__ __forceinline__ void cp_commit() {
    asm volatile("cp.async.commit_group;" ::: "memory");
}
__device__ __forceinline__ void cp_wait1() {
    asm volatile("cp.async.wait_group 1;" ::: "memory");
}
__device__ __forceinline__ void cp_wait0() {
    asm volatile("cp.async.wait_group 0;" ::: "memory");
}
__device__ __forceinline__ void ldmx4(uint32_t* r, uint32_t addr) {
    asm volatile("ldmatrix.sync.aligned.m8n8.x4.shared.b16 {%0,%1,%2,%3}, [%4];"
                 : "=r"(r[0]), "=r"(r[1]), "=r"(r[2]), "=r"(r[3]) : "r"(addr));
}
__device__ __forceinline__ void ldmx2(uint32_t* r, uint32_t addr) {
    asm volatile("ldmatrix.sync.aligned.m8n8.x2.shared.b16 {%0,%1}, [%2];"
                 : "=r"(r[0]), "=r"(r[1]) : "r"(addr));
}
__device__ __forceinline__ void mma16816h(float* c, const uint32_t* a, const uint32_t* b) {
    asm volatile(
        "mma.sync.aligned.m16n8k16.row.col.f32.f16.f16.f32 "
        "{%0,%1,%2,%3}, {%4,%5,%6,%7}, {%8,%9}, {%0,%1,%2,%3};"
        : "+f"(c[0]), "+f"(c[1]), "+f"(c[2]), "+f"(c[3])
        : "r"(a[0]), "r"(a[1]), "r"(a[2]), "r"(a[3]), "r"(b[0]), "r"(b[1]));
}

__device__ __forceinline__ void issue_A(uint32_t sbase, int bm0, int tid) {
    const uint4* GA = (const uint4*)g_Ah;
#pragma unroll
    for (int t = tid; t < 2048; t += 256) {
        int r = t >> 4, q = t & 15;
        cpasync16(sbase + (uint32_t)(r * (SPE * 2) + q * 16),
                  GA + (size_t)(bm0 + r) * 16 + q);
    }
}

__global__ __launch_bounds__(256, 2)
void denseFinal_kernel(const float* __restrict__ K1, const int* __restrict__ idxw,
                       const float* __restrict__ b0, const float* __restrict__ b1,
                       const float* __restrict__ b2,
                       const float* __restrict__ bias, float* __restrict__ out) {
    extern __shared__ __align__(16) char smf[];
    uint32_t sbase = smem_u32(smf);
    int tid  = threadIdx.x;
    int wid  = tid >> 5, lane = tid & 31;
    int id   = blockIdx.y * 32 + blockIdx.x;    // 0..255
    int bm0A = id * 64;
    int bn0  = blockIdx.x * 128;

    // ---- B-weight tile cp.async at kernel entry (group 0): hides under all of phase A ----
    const uint4* GW = (const uint4*)g_Wh;
#pragma unroll
    for (int t = tid; t < 2048; t += 256) {
        int r = t >> 4, q = t & 15;
        cpasync16(sbase + OFF_B + (uint32_t)(r * (SPE * 2) + q * 16),
                  GW + (size_t)(bn0 + r) * 16 + q);
    }
    cp_commit();

    // ---------- phase A0: klo (jobs 128..239) || phi (jobs 0..127) ----------
    if (id < 128) {
        // phi: Phi[hi] columns [bhalf*16, +16), K staged in 32KB k-halves
        int hi    = id & 63;
        int bhalf = id >> 6;
        float* Ksh = (float*)(smf + AK_OFF);
        float* Z0  = (float*)(smf + APHI_OFF);
        float* Z1  = Z0 + 2048;
        float4* Ksh4 = (float4*)Ksh;

        for (int i = tid; i < 2048; i += 256) {
            int l = i >> 4, bb = i & 15;
            Z0[i] = g_z0[(bhalf * 16 + bb) * L + l];
        }
        __syncthreads();

        float* Zin = Z0; float* Zout = Z1;
        int bb = tid & 15;
        int ig = tid >> 4;

        for (int j = 0; j < 6; j++) {
            if ((hi >> j) & 1) {
                const float4* Kp4 = (const float4*)(g_Kpow + (size_t)(3 + j) * L * L);
                float acc[8];
#pragma unroll
                for (int i = 0; i < 8; i++) acc[i] = 0.f;
#pragma unroll
                for (int kh = 0; kh < 2; kh++) {
#pragma unroll
                    for (int i = tid; i < 2048; i += 256) {
                        int row = i >> 4, q = i & 15;
                        Ksh4[i] = Kp4[row * 32 + kh * 16 + q];
                    }
                    __syncthreads();
                    for (int k4 = 0; k4 < 16; k4++) {
                        float z0v = Zin[(kh * 64 + 4 * k4 + 0) * 16 + bb];
                        float z1v = Zin[(kh * 64 + 4 * k4 + 1) * 16 + bb];
                        float z2v = Zin[(kh * 64 + 4 * k4 + 2) * 16 + bb];
                        float z3v = Zin[(kh * 64 + 4 * k4 + 3) * 16 + bb];
#pragma unroll
                        for (int i = 0; i < 8; i++) {
                            float4 kr = Ksh4[(ig * 8 + i) * 16 + k4];
                            acc[i] += kr.x * z0v + kr.y * z1v + kr.z * z2v + kr.w * z3v;
                        }
                    }
                    __syncthreads();
                }
#pragma unroll
                for (int i = 0; i < 8; i++)
                    Zout[(ig * 8 + i) * 16 + bb] = acc[i];
                __syncthreads();
                float* tp = Zin; Zin = Zout; Zout = tp;
            }
        }
        for (int i = tid; i < 2048; i += 256) {
            int l = i >> 4, b2 = i & 15;
            g_Phi[(size_t)hi * L * BZ + l * 32 + bhalf * 16 + b2] = Zin[i];
        }
    } else if (id < 240) {
        // klo: K^l band, factor staged in contiguous 32KB k-halves
        float* Fsh = (float*)(smf + AK_OFF);
        float* S   = (float*)(smf + APHI_OFF);
        float* T   = S + 2048;
        float4* Fsh4 = (float4*)Fsh;
        int u    = id - 128;
        int l    = (u >> 3) + 2;
        int band = u & 7;

        const float* fac[4]; int nf = 0;
        if (l & 1) fac[nf++] = K1;
        if (l & 2) fac[nf++] = g_Kpow + 0 * L * L;
        if (l & 4) fac[nf++] = g_Kpow + 1 * L * L;
        if (l & 8) fac[nf++] = g_Kpow + 2 * L * L;

        const float4* f0 = (const float4*)(fac[0] + (size_t)band * 16 * L);
#pragma unroll
        for (int i = tid; i < 512; i += 256) ((float4*)S)[i] = f0[i];
        __syncthreads();

        float* in = S; float* out2 = T;
        for (int f = 1; f < nf; f++) {
            int n  = tid & 127;
            int r0 = (tid >> 7) * 8;
            float acc[8];
#pragma unroll
            for (int i = 0; i < 8; i++) acc[i] = 0.f;
#pragma unroll
            for (int kh = 0; kh < 2; kh++) {
                const float4* F4 = (const float4*)(fac[f] + kh * 64 * L);
#pragma unroll
                for (int i = tid; i < 2048; i += 256) Fsh4[i] = F4[i];
                __syncthreads();
#pragma unroll 4
                for (int k = 0; k < 64; k++) {
                    float w = Fsh[k * L + n];
#pragma unroll
                    for (int i = 0; i < 8; i++) acc[i] += in[(r0 + i) * L + kh * 64 + k] * w;
                }
                __syncthreads();
            }
#pragma unroll
            for (int i = 0; i < 8; i++) out2[(r0 + i) * L + n] = acc[i];
            __syncthreads();
            float* tp = in; in = out2; out2 = tp;
        }
        float* dst = g_Klo + (size_t)l * L * L + (size_t)band * 16 * L;
#pragma unroll
        for (int i = tid; i < 512; i += 256) ((float4*)dst)[i] = ((float4*)in)[i];
    }

    gridbar(&g_bar[11], 256);   // klo/Phi visible to all CTAs

    // ---------- phase A1: fused apply (fp32, K staged in 32KB halves) -> fp16 tile at XA2 ----------
    {
        bool is64 = ((idxw[1] | idxw[3] | idxw[5] | idxw[7] | idxw[9] | idxw[11]) == 0);
        int b  = tid & 31;
        int ig = tid >> 5;
        float* Ksh  = (float*)(smf + AK_OFF);
        float* sPhi = (float*)(smf + APHI_OFF);
        float4* Ksh4 = (float4*)Ksh;

        for (int tt = 0; tt < 2; tt++) {
            int t = id * 2 + tt;
            int e = is64 ? (idxw[2 * t] - idxw[0]) : (idxw[t] - idxw[0]);
            int lo = e & 15, hi = e >> 4;

            const float4* ps = (const float4*)(g_Phi + (size_t)hi * L * BZ);
#pragma unroll
            for (int i = tid; i < 1024; i += 256) ((float4*)sPhi)[i] = ps[i];

            float acc[16];
            if (lo != 0) {
                const float* Kp = (lo == 1) ? K1 : (g_Klo + (size_t)lo * L * L);
                const float4* Kp4 = (const float4*)Kp;
#pragma unroll
                for (int i = 0; i < 16; i++) acc[i] = 0.f;
#pragma unroll
                for (int kh = 0; kh < 2; kh++) {
#pragma unroll
                    for (int i = tid; i < 2048; i += 256) {
                        int row = i >> 4, q = i & 15;
                        Ksh4[i] = Kp4[row * 32 + kh * 16 + q];
                    }
                    __syncthreads();
                    for (int k4 = 0; k4 < 16; k4++) {
                        float z0v = sPhi[(kh * 64 + 4 * k4 + 0) * 32 + b];
                        float z1v = sPhi[(kh * 64 + 4 * k4 + 1) * 32 + b];
                        float z2v = sPhi[(kh * 64 + 4 * k4 + 2) * 32 + b];
                        float z3v = sPhi[(kh * 64 + 4 * k4 + 3) * 32 + b];
#pragma unroll
                        for (int i = 0; i < 16; i++) {
                            float4 kr = Ksh4[(ig * 16 + i) * 16 + k4];
                            acc[i] += kr.x * z0v + kr.y * z1v + kr.z * z2v + kr.w * z3v;
                        }
                    }
                    __syncthreads();
                }
            } else {
                __syncthreads();
#pragma unroll
                for (int i = 0; i < 16; i++) acc[i] = sPhi[(ig * 16 + i) * 32 + b];
            }

            __half2 hh[8];
#pragma unroll
            for (int j = 0; j < 8; j++) hh[j] = __floats2half2_rn(acc[2 * j], acc[2 * j + 1]);
            uint4* dst = (uint4*)(smf + XA2_OFF + (tt * 32 + b) * (SPE * 2) + ig * 32);
            dst[0] = ((uint4*)hh)[0];
            dst[1] = ((uint4*)hh)[1];
            __syncthreads();
        }
    }

    // ---------- phase A2: 3 hidden layers on fp16 tensor cores ----------
    {
        int rg = wid & 3;
        int cg = wid >> 2;
        uint32_t aoff = (uint32_t)((rg * 16 + (lane & 15)) * (SPE * 2)) + ((lane >> 4) << 4);
        uint32_t boff[4];
#pragma unroll
        for (int p = 0; p < 4; p++) {
            int row = cg * 64 + p * 16 + ((lane >> 4) << 3) + (lane & 7);
            boff[p] = (uint32_t)(row * (SPE * 2)) + (((lane >> 3) & 1) << 4);
        }
        int g  = lane >> 2;
        int cc = (lane & 3) * 2;
        const float* bl[3] = {b0, b1, b2};

        uint32_t inOff = XA2_OFF, outOff = XB2_OFF;
#pragma unroll
        for (int layer = 0; layer < 3; layer++) {
            const uint4* Wg = (const uint4*)(g_Whid + (size_t)layer * L * L);
#pragma unroll
            for (int i = tid; i < 2048; i += 256) {
                int r = i >> 4, q = i & 15;
                *(uint4*)(smf + WH2_OFF + r * (SPE * 2) + q * 16) = Wg[r * 16 + q];
            }
            __syncthreads();

            float c[8][4];
#pragma unroll
            for (int p = 0; p < 8; p++)
#pragma unroll
                for (int j = 0; j < 4; j++) c[p][j] = 0.f;

#pragma unroll
            for (int k0 = 0; k0 < 8; k0++) {
                uint32_t koff = (uint32_t)(k0 * 32);
                uint32_t a[4];
                ldmx4(a, sbase + inOff + aoff + koff);
#pragma unroll
                for (int p = 0; p < 4; p++) {
                    uint32_t bf[4];
                    ldmx4(bf, sbase + WH2_OFF + boff[p] + koff);
                    mma16816h(c[2 * p + 0], a, bf + 0);
                    mma16816h(c[2 * p + 1], a, bf + 2);
                }
            }

#pragma unroll
            for (int p = 0; p < 8; p++) {
                int col = cg * 64 + p * 8 + cc;
                float bx = bl[layer][col], by = bl[layer][col + 1];
                int row0 = rg * 16 + g;
                float v0x = fmaxf(c[p][0] + bx, 0.f), v0y = fmaxf(c[p][1] + by, 0.f);
                float v1x = fmaxf(c[p][2] + bx, 0.f), v1y = fmaxf(c[p][3] + by, 0.f);
                __half2 h0 = __floats2half2_rn(v0x, v0y);
                __half2 h1 = __floats2half2_rn(v1x, v1y);
                if (layer < 2) {
                    *(uint32_t*)(smf + outOff + row0 * (SPE * 2) + col * 2)       = *(uint32_t*)&h0;
                    *(uint32_t*)(smf + outOff + (row0 + 8) * (SPE * 2) + col * 2) = *(uint32_t*)&h1;
                } else {
                    *(uint32_t*)(g_Ah + (size_t)(bm0A + row0) * L + col)     = *(uint32_t*)&h0;
                    *(uint32_t*)(g_Ah + (size_t)(bm0A + row0 + 8) * L + col) = *(uint32_t*)&h1;
                }
            }
            __syncthreads();
            uint32_t tp = inOff; inOff = outOff; outOff = tp;
        }
    }

    gridbar(&g_bar[10], 256);   // g_Ah visible to all CTAs

    // ---------- phase B: final fp16 tensor-core GEMM ----------
    issue_A(sbase + OFF_A0, blockIdx.y * 128, tid);
    cp_commit();

    int wm = wid >> 2, wn = wid & 3;

    uint32_t a_off[4], b_off[4];
#pragma unroll
    for (int mi = 0; mi < 4; mi++) {
        int row = wm * 64 + mi * 16 + (lane & 15);
        a_off[mi] = (uint32_t)(row * SPE * 2) + ((lane >> 4) << 4);
    }
#pragma unroll
    for (int ni = 0; ni < 4; ni++) {
        int row = wn * 32 + ni * 8 + (lane & 7);
        b_off[ni] = (uint32_t)(row * SPE * 2) + (((lane >> 3) & 1) << 4);
    }
    uint32_t sB = sbase + OFF_B;

    int g  = lane >> 2;
    int cc = (lane & 3) * 2;
    float2 br[4];
#pragma unroll
    for (int ni = 0; ni < 4; ni++) {
        int col = bn0 + wn * 32 + ni * 8 + cc;
        br[ni] = make_float2(bias[col], bias[col + 1]);
    }

    const int NT = 16;
    for (int it = 0; it < NT; it++) {
        int bm0 = (blockIdx.y + 8 * it) * 128;
        if (it + 1 < NT) {
            issue_A(sbase + ((it + 1) & 1 ? OFF_A1 : OFF_A0),
                    (blockIdx.y + 8 * (it + 1)) * 128, tid);
            cp_commit();
            cp_wait1();
        } else {
            cp_wait0();
        }
        __syncthreads();

        uint32_t sA = sbase + ((it & 1) ? OFF_A1 : OFF_A0);
        float c[4][4][4];
#pragma unroll
        for (int mi = 0; mi < 4; mi++)
#pragma unroll
            for (int ni = 0; ni < 4; ni++)
#pragma unroll
                for (int j = 0; j < 4; j++) c[mi][ni][j] = 0.f;

#pragma unroll
        for (int k0 = 0; k0 < 8; k0++) {
            uint32_t koff = (uint32_t)(k0 * 32);
            uint32_t b[4][2];
#pragma unroll
            for (int ni = 0; ni < 4; ni++) ldmx2(b[ni], sB + b_off[ni] + koff);
#pragma unroll
            for (int mi = 0; mi < 4; mi++) {
                uint32_t a[4];
                ldmx4(a, sA + a_off[mi] + koff);
#pragma unroll
                for (int ni = 0; ni < 4; ni++)
                    mma16816h(c[mi][ni], a, b[ni]);
            }
        }

#pragma unroll
        for (int ni = 0; ni < 4; ni++) {
            int col = bn0 + wn * 32 + ni * 8 + cc;
#pragma unroll
            for (int mi = 0; mi < 4; mi++) {
                size_t row = (size_t)(bm0 + wm * 64 + mi * 16 + g);
                float2 v0 = make_float2(c[mi][ni][0] + br[ni].x, c[mi][ni][1] + br[ni].y);
                float2 v1 = make_float2(c[mi][ni][2] + br[ni].x, c[mi][ni][3] + br[ni].y);
                *(float2*)(out + row * DD + col)       = v0;
                *(float2*)(out + (row + 8) * DD + col) = v1;
            }
        }
        __syncthreads();
    }
}

// ---------------- launch ----------------
extern "C" void kernel_launch(void* const* d_in, const int* in_sizes, int n_in,
                              void* d_out, int out_size) {
    const float* x0  = (const float*)d_in[0];
    const int*   idx = (const int*)  d_in[1];
    const float* K   = (const float*)d_in[2];
    const float* We0 = (const float*)d_in[3];
    const float* be0 = (const float*)d_in[4];
    const float* We1 = (const float*)d_in[5];
    const float* be1 = (const float*)d_in[6];
    const float* We2 = (const float*)d_in[7];
    const float* be2 = (const float*)d_in[8];
    const float* We3 = (const float*)d_in[9];
    const float* be3 = (const float*)d_in[10];
    const float* Wd0 = (const float*)d_in[11];
    const float* bd0 = (const float*)d_in[12];
    const float* Wd1 = (const float*)d_in[13];
    const float* bd1 = (const float*)d_in[14];
    const float* Wd2 = (const float*)d_in[15];
    const float* bd2 = (const float*)d_in[16];
    const float* Wd3 = (const float*)d_in[17];
    const float* bd3 = (const float*)d_in[18];
    float* out = (float*)d_out;

    const int smem_ek = 64 * 1024;   // 3 CTAs/SM -> 332 CTAs single wave
    const int smem_df = FSM_BYTES;   // ~102 KB, 2 CTAs/SM -> 256 CTAs single wave
    cudaFuncSetAttribute(encKpow_kernel,    cudaFuncAttributeMaxDynamicSharedMemorySize, smem_ek);
    cudaFuncSetAttribute(denseFinal_kernel, cudaFuncAttributeMaxDynamicSharedMemorySize, smem_df);

    // 1: kpow chain || encoder || weight converts (single wave, true overlap)
    encKpow_kernel<<<332, 256, smem_ek>>>(x0, K, We0, be0, We1, be1, We2, be2, We3, be3,
                                          Wd0, Wd1, Wd2, Wd3);
    // 2: klo/phi + apply + fp16 hiddens + final tensor-core GEMM (fully fused persistent)
    dim3 fgrid(DD / 128, 8);
    denseFinal_kernel<<<fgrid, 256, smem_df>>>(K, idx, bd0, bd1, bd2, bd3, out);
}

// round 14
// speedup vs baseline: 1.1031x; 1.1031x over previous
#include <cuda_runtime.h>
#include <cuda_fp16.h>
#include <stdint.h>

#define L   128
#define BZ  32
#define TT  512
#define DD  4096
#define MT  (TT*BZ)   // 16384 decoder rows

// ---------------- scratch (device globals; no allocation) ----------------
__device__ float g_h1p[8 * BZ * L];          // enc0 split-K partials
__device__ float g_z0[BZ * L];
__device__ float g_Kpow[9 * L * L];          // K^2 .. K^512
__device__ float g_Klo[16 * L * L];          // K^lo
__device__ float g_Phi[64 * L * BZ];         // (K^16)^hi @ z0^T, [hi][l][b]
__device__ __half g_Ah[MT * L];              // last hidden activations, fp16
__device__ __half g_Wh[DD * L];              // Wd3 transposed [n][k], fp16
__device__ __half g_Whid[3 * L * L];         // Wd0..2 transposed [n][k], fp16
__device__ int g_bar[16];                    // monotonic ticket barriers (never reset)

// ticket grid barrier: monotonic counter, safe across graph replays
__device__ __forceinline__ void gridbar(int* ctr, int n) {
    __threadfence();
    __syncthreads();
    if (threadIdx.x == 0) {
        int t = atomicAdd(ctr, 1);
        int target = (t / n + 1) * n;
        while (*(volatile int*)ctr < target) {}
        __threadfence();
    }
    __syncthreads();
}

// ================= launch 1 "mega": kpow || encoder->phi || cvt->klo =================
// 304 CTAs, 256 thr, 64 KB smem, __launch_bounds__(256,3) -> 3 CTAs/SM -> single wave.
// bar[1+p] n=64: kpow steps. bar[14] n=176: K8 ready (kpow+klo). bar[12] n=128: z0 ready.
// bar[13] n=192: chain done (kpow+phi). bar[0] n=128: enc partials.
__global__ __launch_bounds__(256, 3)
void megaA_kernel(const float* __restrict__ x0, const float* __restrict__ K1,
                  const float* __restrict__ W0, const float* __restrict__ b0,
                  const float* __restrict__ W1, const float* __restrict__ b1,
                  const float* __restrict__ W2, const float* __restrict__ b2,
                  const float* __restrict__ W3, const float* __restrict__ b3,
                  const float* __restrict__ Wd0, const float* __restrict__ Wd1,
                  const float* __restrict__ Wd2, const float* __restrict__ Wd3) {
    extern __shared__ float sm1[];
    int tid = threadIdx.x;     // 0..255
    int n   = tid & 127;
    int grp = tid >> 7;        // 0/1
    int bid = blockIdx.x;

    if (bid < 64) {
        // ---------------- kpow chain: 2 rows per CTA, A smem-resident ----------------
        float* As = sm1;       // 64 KB
        float4* As4 = (float4*)As;
        int row = bid * 2 + grp;
        const float* A = K1;
        for (int p = 0; p < 9; p++) {
            float* C = g_Kpow + (size_t)p * L * L;
            const float4* A4 = (const float4*)A;
#pragma unroll
            for (int q = tid; q < 4096; q += 256) As4[q] = A4[q];
            __syncthreads();
            const float* rowA = As + row * L;
            float a0 = 0.f, a1 = 0.f, a2 = 0.f, a3 = 0.f;
#pragma unroll 8
            for (int k = 0; k < L; k += 4) {
                a0 += rowA[k + 0] * As[(k + 0) * L + n];
                a1 += rowA[k + 1] * As[(k + 1) * L + n];
                a2 += rowA[k + 2] * As[(k + 2) * L + n];
                a3 += rowA[k + 3] * As[(k + 3) * L + n];
            }
            C[row * L + n] = (a0 + a1) + (a2 + a3);
            __syncthreads();
            gridbar(&g_bar[1 + p], 64);
            if (p == 2) gridbar(&g_bar[14], 176);   // release klo (K2,K4,K8 ready)
            A = C;
        }
        gridbar(&g_bar[13], 192);                    // release phi (full chain ready)
        return;
    }

    if (bid < 192) {
        // ---------------- encoder split-K (2 jobs/CTA), tail on CTA 64, then phi ----------------
        {
            float* xs = sm1 + grp * 512;
            int job = (bid - 64) * 2 + grp;
            int row = job >> 3, c = job & 7;
            const float4* src = (const float4*)(x0 + (size_t)row * DD + c * 512);
            ((float4*)xs)[n] = src[n];
            __syncthreads();
            float a0 = 0.f, a1 = 0.f, a2 = 0.f, a3 = 0.f;
            const float* Wc = W0 + (size_t)(c * 512) * L;
#pragma unroll 8
            for (int k = 0; k < 512; k += 4) {
                a0 += xs[k + 0] * Wc[(size_t)(k + 0) * L + n];
                a1 += xs[k + 1] * Wc[(size_t)(k + 1) * L + n];
                a2 += xs[k + 2] * Wc[(size_t)(k + 2) * L + n];
                a3 += xs[k + 3] * Wc[(size_t)(k + 3) * L + n];
            }
            g_h1p[(c * BZ + row) * L + n] = (a0 + a1) + (a2 + a3);
        }
        gridbar(&g_bar[0], 128);

        if (bid == 64) {
            // ---- tail: reduce + 3 layers, W staged in 32KB halves ----
            float* Ws = sm1;
            float* Xa = sm1 + 8192;
            float* Xb = sm1 + 12288;
            float4* Ws4 = (float4*)Ws;
            int r0 = grp * 16;
            __syncthreads();   // xs reads done (enc phase) before Ws overwrite

#pragma unroll
            for (int r = 0; r < 16; r++) {
                float s = 0.f;
#pragma unroll
                for (int c2 = 0; c2 < 8; c2++) s += g_h1p[(c2 * BZ + r0 + r) * L + n];
                Xa[(r0 + r) * L + n] = fmaxf(s + b0[n], 0.f);
            }
            __syncthreads();

            const float* Wl[3] = {W1, W2, W3};
            const float* bl[3] = {b1, b2, b3};
            float* Xi = Xa; float* Xo = Xb;
#pragma unroll
            for (int layer = 0; layer < 3; layer++) {
                float acc[16];
#pragma unroll
                for (int r = 0; r < 16; r++) acc[r] = 0.f;
#pragma unroll
                for (int half = 0; half < 2; half++) {
                    const float4* W4 = (const float4*)(Wl[layer] + half * 64 * L);
#pragma unroll
                    for (int q = tid; q < 2048; q += 256) Ws4[q] = W4[q];
                    __syncthreads();
#pragma unroll 4
                    for (int k = 0; k < 64; k++) {
                        float w = Ws[k * L + n];
#pragma unroll
                        for (int r = 0; r < 16; r++) acc[r] += Xi[(r0 + r) * L + half * 64 + k] * w;
                    }
                    __syncthreads();
                }
                float bn = bl[layer][n];
                if (layer < 2) {
#pragma unroll
                    for (int r = 0; r < 16; r++) Xo[(r0 + r) * L + n] = fmaxf(acc[r] + bn, 0.f);
                    __syncthreads();
                    float* tp = Xi; Xi = Xo; Xo = tp;
                } else {
#pragma unroll
                    for (int r = 0; r < 16; r++) g_z0[(r0 + r) * L + n] = acc[r] + bn;
                }
            }
            __threadfence();
        }
        gridbar(&g_bar[12], 128);   // z0 ready (CTA 64 arrives after tail)
        gridbar(&g_bar[13], 192);   // wait for kpow chain

        // ---------------- phi: Phi[hi] cols [bhalf*16,+16), K staged in 32KB halves ----------------
        {
            int u     = bid - 64;
            int hi    = u & 63;
            int bhalf = u >> 6;
            float* Ksh = sm1;                 // 8192 floats
            float* Z0  = sm1 + 8192;          // 2048 floats
            float* Z1  = Z0 + 2048;
            float4* Ksh4 = (float4*)Ksh;

            __syncthreads();
            for (int i = tid; i < 2048; i += 256) {
                int l = i >> 4, bb = i & 15;
                Z0[i] = g_z0[(bhalf * 16 + bb) * L + l];
            }
            __syncthreads();

            float* Zin = Z0; float* Zout = Z1;
            int bb = tid & 15;
            int ig = tid >> 4;

            for (int j = 0; j < 6; j++) {
                if ((hi >> j) & 1) {
                    const float4* Kp4 = (const float4*)(g_Kpow + (size_t)(3 + j) * L * L);
                    float acc[8];
#pragma unroll
                    for (int i = 0; i < 8; i++) acc[i] = 0.f;
#pragma unroll
                    for (int kh = 0; kh < 2; kh++) {
#pragma unroll
                        for (int i = tid; i < 2048; i += 256) {
                            int row = i >> 4, q = i & 15;
                            Ksh4[i] = Kp4[row * 32 + kh * 16 + q];
                        }
                        __syncthreads();
                        for (int k4 = 0; k4 < 16; k4++) {
                            float z0v = Zin[(kh * 64 + 4 * k4 + 0) * 16 + bb];
                            float z1v = Zin[(kh * 64 + 4 * k4 + 1) * 16 + bb];
                            float z2v = Zin[(kh * 64 + 4 * k4 + 2) * 16 + bb];
                            float z3v = Zin[(kh * 64 + 4 * k4 + 3) * 16 + bb];
#pragma unroll
                            for (int i = 0; i < 8; i++) {
                                float4 kr = Ksh4[(ig * 8 + i) * 16 + k4];
                                acc[i] += kr.x * z0v + kr.y * z1v + kr.z * z2v + kr.w * z3v;
                            }
                        }
                        __syncthreads();
                    }
#pragma unroll
                    for (int i = 0; i < 8; i++)
                        Zout[(ig * 8 + i) * 16 + bb] = acc[i];
                    __syncthreads();
                    float* tp = Zin; Zin = Zout; Zout = tp;
                }
            }
            for (int i = tid; i < 2048; i += 256) {
                int l = i >> 4, b2 = i & 15;
                g_Phi[(size_t)hi * L * BZ + l * 32 + bhalf * 16 + b2] = Zin[i];
            }
        }
        return;
    }

    // ---------------- CTAs 192..303: weight converts (1-2 jobs), then klo ----------------
    {
        int base = bid - 192;                   // 0..111
        float (*tile)[33] = (float(*)[33])sm1;
        for (int rep = 0; rep < 2; rep++) {
            int job = base + rep * 112;
            if (job >= 140) break;
            const float* src;
            __half* dstg;
            int n0, stride;
            if (job < 128) {
                n0 = job * 32; src = Wd3; stride = DD; dstg = g_Wh;
            } else {
                int u3 = job - 128;
                int layer = u3 >> 2;
                n0 = (u3 & 3) * 32;
                src = (layer == 0) ? Wd0 : (layer == 1) ? Wd1 : Wd2;
                stride = L;
                dstg = g_Whid + (size_t)layer * L * L;
            }
            int tx = tid & 31, ty = tid >> 5;
            for (int k = ty; k < 128; k += 8)
                tile[k][tx] = src[(size_t)k * stride + n0 + tx];
            __syncthreads();
            int nn = n0 + (tid >> 3);
            int k0 = (tid & 7) * 16;
            int c  = nn - n0;
            __half2 h[8];
#pragma unroll
            for (int j = 0; j < 8; j++)
                h[j] = __floats2half2_rn(tile[k0 + 2 * j][c], tile[k0 + 2 * j + 1][c]);
            uint4* dh = (uint4*)(dstg + (size_t)nn * L + k0);
            dh[0] = ((uint4*)h)[0];
            dh[1] = ((uint4*)h)[1];
            __syncthreads();
        }
    }
    gridbar(&g_bar[14], 176);   // wait for K2,K4,K8

    // ---------------- klo: K^l band, factor staged in 32KB k-halves ----------------
    {
        float* Fsh = sm1;
        float* S   = sm1 + 8192;
        float* T   = S + 2048;
        float4* Fsh4 = (float4*)Fsh;
        int u    = bid - 192;       // 0..111
        int l    = (u >> 3) + 2;
        int band = u & 7;

        const float* fac[4]; int nf = 0;
        if (l & 1) fac[nf++] = K1;
        if (l & 2) fac[nf++] = g_Kpow + 0 * L * L;
        if (l & 4) fac[nf++] = g_Kpow + 1 * L * L;
        if (l & 8) fac[nf++] = g_Kpow + 2 * L * L;

        const float4* f0 = (const float4*)(fac[0] + (size_t)band * 16 * L);
#pragma unroll
        for (int i = tid; i < 512; i += 256) ((float4*)S)[i] = f0[i];
        __syncthreads();

        float* in = S; float* out2 = T;
        for (int f = 1; f < nf; f++) {
            int nn = tid & 127;
            int r0 = (tid >> 7) * 8;
            float acc[8];
#pragma unroll
            for (int i = 0; i < 8; i++) acc[i] = 0.f;
#pragma unroll
            for (int kh = 0; kh < 2; kh++) {
                const float4* F4 = (const float4*)(fac[f] + kh * 64 * L);
#pragma unroll
                for (int i = tid; i < 2048; i += 256) Fsh4[i] = F4[i];
                __syncthreads();
#pragma unroll 4
                for (int k = 0; k < 64; k++) {
                    float w = Fsh[k * L + nn];
#pragma unroll
                    for (int i = 0; i < 8; i++) acc[i] += in[(r0 + i) * L + kh * 64 + k] * w;
                }
                __syncthreads();
            }
#pragma unroll
            for (int i = 0; i < 8; i++) out2[(r0 + i) * L + nn] = acc[i];
            __syncthreads();
            float* tp = in; in = out2; out2 = tp;
        }
        float* dst = g_Klo + (size_t)l * L * L + (size_t)band * 16 * L;
#pragma unroll
        for (int i = tid; i < 512; i += 256) ((float4*)dst)[i] = ((float4*)in)[i];
    }
}

// ================= launch 2: apply + fp16 hiddens + final fp16 GEMM (R12 form, persistent) =================
#define SPE 136
#define TILE_BYTES (128 * SPE * 2)      // 34816
#define OFF_B   0
#define OFF_A0  TILE_BYTES
#define OFF_A1  (2 * TILE_BYTES)
#define FSM_BYTES (3 * TILE_BYTES)      // 104448

#define KS_OFF   0
#define PHI_OFF  65536
#define XA_OFF   81920
#define WH_OFF   0
#define XB_OFF   40960

__device__ __forceinline__ uint32_t smem_u32(const void* p) {
    uint32_t a;
    asm("{ .reg .u64 t; cvta.to.shared.u64 t, %1; cvt.u32.u64 %0, t; }" : "=r"(a) : "l"(p));
    return a;
}
__device__ __forceinline__ void cpasync16(uint32_t dst, const void* src) {
    asm volatile("cp.async.cg.shared.global [%0], [%1], 16;" :: "r"(dst), "l"(src));
}
__device__ __forceinline__ void cp_commit() {
    asm volatile("cp.async.commit_group;" ::: "memory");
}
__device__ __forceinline__ void cp_wait1() {
    asm volatile("cp.async.wait_group 1;" ::: "memory");
}
__device__ __forceinline__ void cp_wait0() {
    asm volatile("cp.async.wait_group 0;" ::: "memory");
}
__device__ __forceinline__ void ldmx4(uint32_t* r, uint32_t addr) {
    asm volatile("ldmatrix.sync.aligned.m8n8.x4.shared.b16 {%0,%1,%2,%3}, [%4];"
                 : "=r"(r[0]), "=r"(r[1]), "=r"(r[2]), "=r"(r[3]) : "r"(addr));
}
__device__ __forceinline__ void ldmx2(uint32_t* r, uint32_t addr) {
    asm volatile("ldmatrix.sync.aligned.m8n8.x2.shared.b16 {%0,%1}, [%2];"
                 : "=r"(r[0]), "=r"(r[1]) : "r"(addr));
}
__device__ __forceinline__ void mma16816h(float* c, const uint32_t* a, const uint32_t* b) {
    asm volatile(
        "mma.sync.aligned.m16n8k16.row.col.f32.f16.f16.f32 "
        "{%0,%1,%2,%3}, {%4,%5,%6,%7}, {%8,%9}, {%0,%1,%2,%3};"
        : "+f"(c[0]), "+f"(c[1]), "+f"(c[2]), "+f"(c[3])
        : "r"(a[0]), "r"(a[1]), "r"(a[2]), "r"(a[3]), "r"(b[0]), "r"(b[1]));
}

__device__ __forceinline__ void issue_A(uint32_t sbase, int bm0, int tid) {
    const uint4* GA = (const uint4*)g_Ah;
#pragma unroll
    for (int t = tid; t < 2048; t += 256) {
        int r = t >> 4, q = t & 15;
        cpasync16(sbase + (uint32_t)(r * (SPE * 2) + q * 16),
                  GA + (size_t)(bm0 + r) * 16 + q);
    }
}

__global__ __launch_bounds__(256, 2)
void denseFinal_kernel(const float* __restrict__ K1, const int* __restrict__ idxw,
                       const float* __restrict__ b0, const float* __restrict__ b1,
                       const float* __restrict__ b2,
                       const float* __restrict__ bias, float* __restrict__ out) {
    extern __shared__ __align__(16) char smf[];
    uint32_t sbase = smem_u32(smf);
    int tid  = threadIdx.x;
    int wid  = tid >> 5, lane = tid & 31;
    int id   = blockIdx.y * 32 + blockIdx.x;
    int bm0A = id * 64;

    // ---------- phase A1: fused apply (fp32): Z rows -> fp16 tile at XA_OFF ----------
    {
        bool is64 = ((idxw[1] | idxw[3] | idxw[5] | idxw[7] | idxw[9] | idxw[11]) == 0);
        int b  = tid & 31;
        int ig = tid >> 5;
        float* Ks   = (float*)(smf + KS_OFF);
        float* sPhi = (float*)(smf + PHI_OFF);

        for (int tt = 0; tt < 2; tt++) {
            int t = id * 2 + tt;
            int e = is64 ? (idxw[2 * t] - idxw[0]) : (idxw[t] - idxw[0]);
            int lo = e & 15, hi = e >> 4;

            const float4* ps = (const float4*)(g_Phi + (size_t)hi * L * BZ);
#pragma unroll
            for (int i = tid; i < 1024; i += 256) ((float4*)sPhi)[i] = ps[i];

            float acc[16];
            if (lo != 0) {
                const float* Kp = (lo == 1) ? K1 : (g_Klo + (size_t)lo * L * L);
#pragma unroll
                for (int i = tid; i < 4096; i += 256) ((float4*)Ks)[i] = ((const float4*)Kp)[i];
                __syncthreads();
#pragma unroll
                for (int i = 0; i < 16; i++) acc[i] = 0.f;
                for (int k4 = 0; k4 < 32; k4++) {
                    float z0v = sPhi[(4 * k4 + 0) * 32 + b];
                    float z1v = sPhi[(4 * k4 + 1) * 32 + b];
                    float z2v = sPhi[(4 * k4 + 2) * 32 + b];
                    float z3v = sPhi[(4 * k4 + 3) * 32 + b];
#pragma unroll
                    for (int i = 0; i < 16; i++) {
                        float4 kr = ((const float4*)Ks)[(ig * 16 + i) * 32 + k4];
                        acc[i] += kr.x * z0v + kr.y * z1v + kr.z * z2v + kr.w * z3v;
                    }
                }
            } else {
                __syncthreads();
#pragma unroll
                for (int i = 0; i < 16; i++) acc[i] = sPhi[(ig * 16 + i) * 32 + b];
            }

            __half2 hh[8];
#pragma unroll
            for (int j = 0; j < 8; j++) hh[j] = __floats2half2_rn(acc[2 * j], acc[2 * j + 1]);
            uint4* dst = (uint4*)(smf + XA_OFF + (tt * 32 + b) * (SPE * 2) + ig * 32);
            dst[0] = ((uint4*)hh)[0];
            dst[1] = ((uint4*)hh)[1];
            __syncthreads();
        }
    }

    // ---------- phase A2: 3 hidden layers on fp16 tensor cores ----------
    {
        int rg = wid & 3;
        int cg = wid >> 2;
        uint32_t aoff = (uint32_t)((rg * 16 + (lane & 15)) * (SPE * 2)) + ((lane >> 4) << 4);
        uint32_t boff[4];
#pragma unroll
        for (int p = 0; p < 4; p++) {
            int row = cg * 64 + p * 16 + ((lane >> 4) << 3) + (lane & 7);
            boff[p] = (uint32_t)(row * (SPE * 2)) + (((lane >> 3) & 1) << 4);
        }
        int g  = lane >> 2;
        int cc = (lane & 3) * 2;
        const float* bl[3] = {b0, b1, b2};

        uint32_t inOff = XA_OFF, outOff = XB_OFF;
#pragma unroll
        for (int layer = 0; layer < 3; layer++) {
            const uint4* Wg = (const uint4*)(g_Whid + (size_t)layer * L * L);
#pragma unroll
            for (int i = tid; i < 2048; i += 256) {
                int r = i >> 4, q = i & 15;
                *(uint4*)(smf + WH_OFF + r * (SPE * 2) + q * 16) = Wg[r * 16 + q];
            }
            __syncthreads();

            float c[8][4];
#pragma unroll
            for (int p = 0; p < 8; p++)
#pragma unroll
                for (int j = 0; j < 4; j++) c[p][j] = 0.f;

#pragma unroll
            for (int k0 = 0; k0 < 8; k0++) {
                uint32_t koff = (uint32_t)(k0 * 32);
                uint32_t a[4];
                ldmx4(a, sbase + inOff + aoff + koff);
#pragma unroll
                for (int p = 0; p < 4; p++) {
                    uint32_t bf[4];
                    ldmx4(bf, sbase + WH_OFF + boff[p] + koff);
                    mma16816h(c[2 * p + 0], a, bf + 0);
                    mma16816h(c[2 * p + 1], a, bf + 2);
                }
            }

#pragma unroll
            for (int p = 0; p < 8; p++) {
                int col = cg * 64 + p * 8 + cc;
                float bx = bl[layer][col], by = bl[layer][col + 1];
                int row0 = rg * 16 + g;
                float v0x = fmaxf(c[p][0] + bx, 0.f), v0y = fmaxf(c[p][1] + by, 0.f);
                float v1x = fmaxf(c[p][2] + bx, 0.f), v1y = fmaxf(c[p][3] + by, 0.f);
                __half2 h0 = __floats2half2_rn(v0x, v0y);
                __half2 h1 = __floats2half2_rn(v1x, v1y);
                if (layer < 2) {
                    *(uint32_t*)(smf + outOff + row0 * (SPE * 2) + col * 2)       = *(uint32_t*)&h0;
                    *(uint32_t*)(smf + outOff + (row0 + 8) * (SPE * 2) + col * 2) = *(uint32_t*)&h1;
                } else {
                    *(uint32_t*)(g_Ah + (size_t)(bm0A + row0) * L + col)     = *(uint32_t*)&h0;
                    *(uint32_t*)(g_Ah + (size_t)(bm0A + row0 + 8) * L + col) = *(uint32_t*)&h1;
                }
            }
            __syncthreads();
            uint32_t tp = inOff; inOff = outOff; outOff = tp;
        }
    }

    gridbar(&g_bar[10], 256);

    // ---------- phase B: final fp16 tensor-core GEMM ----------
    int bn0 = blockIdx.x * 128;

    const uint4* GW = (const uint4*)g_Wh;
#pragma unroll
    for (int t = tid; t < 2048; t += 256) {
        int r = t >> 4, q = t & 15;
        cpasync16(sbase + OFF_B + (uint32_t)(r * (SPE * 2) + q * 16),
                  GW + (size_t)(bn0 + r) * 16 + q);
    }
    cp_commit();

    issue_A(sbase + OFF_A0, blockIdx.y * 128, tid);
    cp_commit();

    int wm = wid >> 2, wn = wid & 3;

    uint32_t a_off[4], b_off[4];
#pragma unroll
    for (int mi = 0; mi < 4; mi++) {
        int row = wm * 64 + mi * 16 + (lane & 15);
        a_off[mi] = (uint32_t)(row * SPE * 2) + ((lane >> 4) << 4);
    }
#pragma unroll
    for (int ni = 0; ni < 4; ni++) {
        int row = wn * 32 + ni * 8 + (lane & 7);
        b_off[ni] = (uint32_t)(row * SPE * 2) + (((lane >> 3) & 1) << 4);
    }
    uint32_t sB = sbase + OFF_B;

    int g  = lane >> 2;
    int cc = (lane & 3) * 2;
    float2 br[4];
#pragma unroll
    for (int ni = 0; ni < 4; ni++) {
        int col = bn0 + wn * 32 + ni * 8 + cc;
        br[ni] = make_float2(bias[col], bias[col + 1]);
    }

    const int NT = 16;
    for (int it = 0; it < NT; it++) {
        int bm0 = (blockIdx.y + 8 * it) * 128;
        if (it + 1 < NT) {
            issue_A(sbase + ((it + 1) & 1 ? OFF_A1 : OFF_A0),
                    (blockIdx.y + 8 * (it + 1)) * 128, tid);
            cp_commit();
            cp_wait1();
        } else {
            cp_wait0();
        }
        __syncthreads();

        uint32_t sA = sbase + ((it & 1) ? OFF_A1 : OFF_A0);
        float c[4][4][4];
#pragma unroll
        for (int mi = 0; mi < 4; mi++)
#pragma unroll
            for (int ni = 0; ni < 4; ni++)
#pragma unroll
                for (int j = 0; j < 4; j++) c[mi][ni][j] = 0.f;

#pragma unroll
        for (int k0 = 0; k0 < 8; k0++) {
            uint32_t koff = (uint32_t)(k0 * 32);
            uint32_t b[4][2];
#pragma unroll
            for (int ni = 0; ni < 4; ni++) ldmx2(b[ni], sB + b_off[ni] + koff);
#pragma unroll
            for (int mi = 0; mi < 4; mi++) {
                uint32_t a[4];
                ldmx4(a, sA + a_off[mi] + koff);
#pragma unroll
                for (int ni = 0; ni < 4; ni++)
                    mma16816h(c[mi][ni], a, b[ni]);
            }
        }

#pragma unroll
        for (int ni = 0; ni < 4; ni++) {
            int col = bn0 + wn * 32 + ni * 8 + cc;
#pragma unroll
            for (int mi = 0; mi < 4; mi++) {
                size_t row = (size_t)(bm0 + wm * 64 + mi * 16 + g);
                float2 v0 = make_float2(c[mi][ni][0] + br[ni].x, c[mi][ni][1] + br[ni].y);
                float2 v1 = make_float2(c[mi][ni][2] + br[ni].x, c[mi][ni][3] + br[ni].y);
                *(float2*)(out + row * DD + col)       = v0;
                *(float2*)(out + (row + 8) * DD + col) = v1;
            }
        }
        __syncthreads();
    }
}

// ---------------- launch ----------------
extern "C" void kernel_launch(void* const* d_in, const int* in_sizes, int n_in,
                              void* d_out, int out_size) {
    const float* x0  = (const float*)d_in[0];
    const int*   idx = (const int*)  d_in[1];
    const float* K   = (const float*)d_in[2];
    const float* We0 = (const float*)d_in[3];
    const float* be0 = (const float*)d_in[4];
    const float* We1 = (const float*)d_in[5];
    const float* be1 = (const float*)d_in[6];
    const float* We2 = (const float*)d_in[7];
    const float* be2 = (const float*)d_in[8];
    const float* We3 = (const float*)d_in[9];
    const float* be3 = (const float*)d_in[10];
    const float* Wd0 = (const float*)d_in[11];
    const float* bd0 = (const float*)d_in[12];
    const float* Wd1 = (const float*)d_in[13];
    const float* bd1 = (const float*)d_in[14];
    const float* Wd2 = (const float*)d_in[15];
    const float* bd2 = (const float*)d_in[16];
    const float* Wd3 = (const float*)d_in[17];
    const float* bd3 = (const float*)d_in[18];
    float* out = (float*)d_out;

    const int smem_mega = 64 * 1024;   // 3 CTAs/SM (enforced) -> 304 CTAs single wave
    const int smem_df   = FSM_BYTES;   // ~102 KB, 2 CTAs/SM -> 256 CTAs single wave
    cudaFuncSetAttribute(megaA_kernel,      cudaFuncAttributeMaxDynamicSharedMemorySize, smem_mega);
    cudaFuncSetAttribute(denseFinal_kernel, cudaFuncAttributeMaxDynamicSharedMemorySize, smem_df);

    // 1: kpow || encoder->phi || cvt->klo (single wave, ticket-barrier dependencies)
    megaA_kernel<<<304, 256, smem_mega>>>(x0, K, We0, be0, We1, be1, We2, be2, We3, be3,
                                          Wd0, Wd1, Wd2, Wd3);
    // 2: apply + fp16 hiddens + final tensor-core GEMM (R12 form)
    dim3 fgrid(DD / 128, 8);
    denseFinal_kernel<<<fgrid, 256, smem_df>>>(K, idx, bd0, bd1, bd2, bd3, out);
}